// round 16
// baseline (speedup 1.0000x reference)
#include <cuda_runtime.h>
#include <cuda_fp16.h>
#include <cstdint>

#define NQ 4096
#define NK 8192
#define DIM 1024
#define KSPLIT 8

// ---------------------------------------------------------------------------
// Scratch (device globals; no allocation in kernel_launch)
// ---------------------------------------------------------------------------
__device__ __half g_Qh[(size_t)NQ * DIM];     //  8 MB fp16 Q
__device__ __half g_Kh[(size_t)NK * DIM];     // 16 MB fp16 K (K-major)
__device__ __half g_Vt[(size_t)DIM * NK];     // 16 MB fp16 V^T [n][k]
__device__ __half g_R [(size_t)NQ * NK];      // 64 MB fp16 R = exp(cos)-1
__device__ __half g_pv[KSPLIT][(size_t)NQ * DIM];  // 64 MB fp16 PV partials
__device__ float  g_qninv[NQ];
__device__ float  g_kninv[NK];
__device__ float  g_colsum[DIM];
__device__ float  g_knpart[32][NK];           // per-dim-strip |k|^2 partials
__device__ float  g_colpart[256][DIM];        // per-key-strip colsum partials
__device__ float  g_rpart[NK / 128][NQ];      // per-n-tile row partials (GEMM1)

// ---------------------------------------------------------------------------
// PTX helpers (plain sm_103-compatible: mma.sync / ldmatrix / cp.async)
// ---------------------------------------------------------------------------
__device__ __forceinline__ uint32_t smem_u32(const void* p) {
    uint32_t a;
    asm("{ .reg .u64 t; cvta.to.shared.u64 t, %1; cvt.u32.u64 %0, t; }"
        : "=r"(a) : "l"(p));
    return a;
}
__device__ __forceinline__ void cp16(uint32_t dst, const void* src) {
    asm volatile("cp.async.cg.shared.global [%0], [%1], 16;" :: "r"(dst), "l"(src));
}
#define CP_COMMIT() asm volatile("cp.async.commit_group;" ::: "memory")
#define CP_WAIT(N)  asm volatile("cp.async.wait_group %0;" :: "n"(N) : "memory")

__device__ __forceinline__ void ldsm_x4(uint32_t (&r)[4], uint32_t addr) {
    asm volatile("ldmatrix.sync.aligned.m8n8.x4.shared.b16 {%0,%1,%2,%3}, [%4];"
        : "=r"(r[0]), "=r"(r[1]), "=r"(r[2]), "=r"(r[3]) : "r"(addr));
}
__device__ __forceinline__ void mma16816(float (&d)[4], const uint32_t (&a)[4],
                                         uint32_t b0, uint32_t b1) {
    asm volatile("mma.sync.aligned.m16n8k16.row.col.f32.f16.f16.f32 "
        "{%0,%1,%2,%3}, {%4,%5,%6,%7}, {%8,%9}, {%0,%1,%2,%3};"
        : "+f"(d[0]), "+f"(d[1]), "+f"(d[2]), "+f"(d[3])
        : "r"(a[0]), "r"(a[1]), "r"(a[2]), "r"(a[3]), "r"(b0), "r"(b1));
}

// ---------------------------------------------------------------------------
// Aux kernels
// ---------------------------------------------------------------------------
__global__ void convert_norm_kernel(const float* __restrict__ X,
                                    __half* __restrict__ Xh,
                                    float* __restrict__ ninv) {
    int row  = blockIdx.x * 8 + (threadIdx.x >> 5);
    int lane = threadIdx.x & 31;
    const float4* xp = (const float4*)(X + (size_t)row * DIM);
    __half2* op = (__half2*)(Xh + (size_t)row * DIM);
    float s = 0.f;
#pragma unroll
    for (int i = 0; i < 8; i++) {
        float4 v = xp[lane + 32 * i];
        s += v.x * v.x + v.y * v.y + v.z * v.z + v.w * v.w;
        op[(lane + 32 * i) * 2]     = __floats2half2_rn(v.x, v.y);
        op[(lane + 32 * i) * 2 + 1] = __floats2half2_rn(v.z, v.w);
    }
#pragma unroll
    for (int o = 16; o > 0; o >>= 1) s += __shfl_xor_sync(0xffffffffu, s, o);
    if (lane == 0) ninv[row] = rsqrtf(s);
}

__global__ void fuse_k_kernel(const float* __restrict__ K) {
    __shared__ float tile[32][33];
    int n0 = blockIdx.x * 32, k0 = blockIdx.y * 32;
    int t = threadIdx.x;
    int krow = t >> 4;
    int c2   = t & 15;
#pragma unroll
    for (int p = 0; p < 2; p++) {
        int k = krow + 16 * p;
        float2 v = *(const float2*)(K + (size_t)(k0 + k) * DIM + n0 + 2 * c2);
        *(__half2*)(g_Kh + (size_t)(k0 + k) * DIM + n0 + 2 * c2) =
            __floats2half2_rn(v.x, v.y);
        tile[k][2 * c2]     = v.x;
        tile[k][2 * c2 + 1] = v.y;
    }
    __syncthreads();
    {
        int nrow = t >> 3;
        int kc   = t & 7;
#pragma unroll
        for (int p = 0; p < 2; p++) {
            int c = kc + 8 * p;
            __half2 h = __floats2half2_rn(tile[2 * c][nrow], tile[2 * c + 1][nrow]);
            *(__half2*)(g_Vt + (size_t)(n0 + nrow) * NK + k0 + 2 * c) = h;
        }
    }
    if (t < 32) {
        float s = 0.f;
#pragma unroll
        for (int j = 0; j < 32; j++) { float v = tile[t][j]; s += v * v; }
        g_knpart[blockIdx.x][k0 + t] = s;
    } else if (t < 64) {
        int c = t - 32;
        float s = 0.f;
#pragma unroll
        for (int j = 0; j < 32; j++) s += tile[j][c];
        g_colpart[blockIdx.y][n0 + c] = s;
    }
}

__global__ void kfin_kernel() {
    int gid = blockIdx.x * 256 + threadIdx.x;
    float s = 0.f;
#pragma unroll
    for (int j = 0; j < 32; j++) s += g_knpart[j][gid];
    g_kninv[gid] = rsqrtf(s);
    if (gid < DIM) {
        float c = 0.f;
        for (int j = 0; j < 256; j++) c += g_colpart[j][gid];
        g_colsum[gid] = c;
    }
}

// Final: rsum[m] = NK + sum_j rpart[j][m] (recomputed per row, deterministic);
// out = (colsum + sum_s pv[s]) / rsum.  Each thread: one row-chunk of 8.
__global__ void combine_kernel(float* __restrict__ out) {
    int idx = blockIdx.x * 256 + threadIdx.x;       // over NQ*DIM/8
    int m  = idx / (DIM / 8);
    int c8 = (idx % (DIM / 8)) * 8;
    float rsum = (float)NK;
#pragma unroll
    for (int j = 0; j < NK / 128; j++) rsum += g_rpart[j][m];
    float ri = 1.0f / rsum;

    float s[8];
#pragma unroll
    for (int u = 0; u < 8; u++) s[u] = g_colsum[c8 + u];
#pragma unroll
    for (int sp = 0; sp < KSPLIT; sp++) {
        uint4 h4 = *(const uint4*)(g_pv[sp] + (size_t)m * DIM + c8);
        const __half2* h = (const __half2*)&h4;
#pragma unroll
        for (int u = 0; u < 4; u++) {
            float2 f = __half22float2(h[u]);
            s[2 * u] += f.x; s[2 * u + 1] += f.y;
        }
    }
    float4 o0 = make_float4(s[0] * ri, s[1] * ri, s[2] * ri, s[3] * ri);
    float4 o1 = make_float4(s[4] * ri, s[5] * ri, s[6] * ri, s[7] * ri);
    *(float4*)(out + (size_t)m * DIM + c8)     = o0;
    *(float4*)(out + (size_t)m * DIM + c8 + 4) = o1;
}

// ---------------------------------------------------------------------------
// HMMA fp16 GEMM: 128x128x64 tile, 256 threads, 3-stage cp.async, 2 CTA/SM.
// Warp grid 4(m) x 2(n); warp tile 32m x 64n (proven R10/R13 structure).
//   MODE 0: A=Qh[m][k], B=Kh[n][k], kdim=1024, grid z=1 (kstart folded to 0
//           at compile time); epi r=exp(acc*qninv*kninv)-1 -> g_R,
//           row partials -> g_rpart
//   MODE 1: A=R[m][k], B=Vt[n][k], kdim=1024 per split, grid z=KSPLIT;
//           epi: raw fp32 acc -> fp16 partial g_pv[z]
// ---------------------------------------------------------------------------
#define BM 128
#define BN 128
#define BK 64
#define STAGES 3
#define PITCHB 144                             // bytes per 64-half row
#define ST_A_BYTES (BM * PITCHB)               // 18432
#define ST_BYTES   (2 * ST_A_BYTES)            // 36864 (A + B)
#define SMEM_BYTES (STAGES * ST_BYTES + 1024)  // 111616 (stages + rp_s)

template <int MODE>
__global__ __launch_bounds__(256, 2) void hgemm_kernel(
    const __half* __restrict__ A, const __half* __restrict__ B,
    int lda, int ldb, int kdim, float* __restrict__ Cout) {
    extern __shared__ char smem[];
    const uint32_t sbase = smem_u32(smem);
    const int t = threadIdx.x;
    const int m0 = blockIdx.y * BM, n0 = blockIdx.x * BN;
    const int kstart = (MODE == 1) ? (int)blockIdx.z * kdim : 0;
    const int lane = t & 31, w = t >> 5;
    const int wm = w >> 1, wn = w & 1;          // 4 x 2 warp grid; tile 32m x 64n
    const int lrow = lane & 15, lcol = (lane >> 4) * 16;

    const int r_ld = t >> 3;
    const int c_ld = t & 7;
    const __half* aptr[4];
    const __half* bptr[4];
    uint32_t s_off[4];
#pragma unroll
    for (int j = 0; j < 4; j++) {
        int r = r_ld + 32 * j;
        aptr[j] = A + (size_t)(m0 + r) * lda + kstart + c_ld * 8;
        bptr[j] = B + (size_t)(n0 + r) * ldb + kstart + c_ld * 8;
        s_off[j] = r * PITCHB + c_ld * 16;
    }

    auto load_stage = [&](int ci, int st) {
        uint32_t sa = sbase + st * ST_BYTES;
        uint32_t sb = sa + ST_A_BYTES;
        int k0 = ci * BK;
#pragma unroll
        for (int j = 0; j < 4; j++) {
            cp16(sa + s_off[j], aptr[j] + k0);
            cp16(sb + s_off[j], bptr[j] + k0);
        }
    };

    float acc[2][8][4] = {};
    const int KT = kdim / BK;

    load_stage(0, 0); CP_COMMIT();
    load_stage(1, 1); CP_COMMIT();

    int st_cur = 0, st_nxt = 2;
    for (int i = 0; i < KT; i++) {
        CP_WAIT(1);
        __syncthreads();
        if (i + 2 < KT) { load_stage(i + 2, st_nxt); }
        CP_COMMIT();

        uint32_t sa = sbase + st_cur * ST_BYTES;
        uint32_t sb = sa + ST_A_BYTES;
        st_cur = (st_cur == STAGES - 1) ? 0 : st_cur + 1;
        st_nxt = (st_nxt == STAGES - 1) ? 0 : st_nxt + 1;

#pragma unroll
        for (int kk = 0; kk < 4; kk++) {
            uint32_t a[2][4], bf[4][4];
#pragma unroll
            for (int mi = 0; mi < 2; mi++) {
                int row = wm * 32 + mi * 16 + lrow;
                ldsm_x4(a[mi], sa + row * PITCHB + kk * 32 + lcol);
            }
#pragma unroll
            for (int ni = 0; ni < 4; ni++) {
                int row = wn * 64 + ni * 16 + lrow;
                ldsm_x4(bf[ni], sb + row * PITCHB + kk * 32 + lcol);
            }
#pragma unroll
            for (int mi = 0; mi < 2; mi++)
#pragma unroll
                for (int ni = 0; ni < 4; ni++) {
                    mma16816(acc[mi][2 * ni],     a[mi], bf[ni][0], bf[ni][2]);
                    mma16816(acc[mi][2 * ni + 1], a[mi], bf[ni][1], bf[ni][3]);
                }
        }
    }

    // ---- Epilogue ----
    const int g = lane >> 2, q = lane & 3;
    const int rbase = m0 + wm * 32;
    const int cbase = n0 + wn * 64;

    if (MODE == 0) {
        float* rp_s = (float*)(smem + STAGES * ST_BYTES);   // [2][128]
        float rs[2][2] = {};
        float kn[8][2];
#pragma unroll
        for (int nj = 0; nj < 8; nj++) {
            int c = cbase + nj * 8 + q * 2;
            kn[nj][0] = g_kninv[c]; kn[nj][1] = g_kninv[c + 1];
        }
#pragma unroll
        for (int mi = 0; mi < 2; mi++) {
            int r0 = rbase + mi * 16 + g;
            float qi0 = g_qninv[r0], qi1 = g_qninv[r0 + 8];
            __half2* d0 = (__half2*)(g_R + (size_t)r0 * NK);
            __half2* d1 = (__half2*)(g_R + (size_t)(r0 + 8) * NK);
#pragma unroll
            for (int nj = 0; nj < 8; nj++) {
                int c = cbase + nj * 8 + q * 2;
                float e00 = __expf(acc[mi][nj][0] * qi0 * kn[nj][0]) - 1.f;
                float e01 = __expf(acc[mi][nj][1] * qi0 * kn[nj][1]) - 1.f;
                float e10 = __expf(acc[mi][nj][2] * qi1 * kn[nj][0]) - 1.f;
                float e11 = __expf(acc[mi][nj][3] * qi1 * kn[nj][1]) - 1.f;
                rs[mi][0] += e00 + e01;
                rs[mi][1] += e10 + e11;
                d0[c >> 1] = __floats2half2_rn(e00, e01);
                d1[c >> 1] = __floats2half2_rn(e10, e11);
            }
        }
#pragma unroll
        for (int mi = 0; mi < 2; mi++)
#pragma unroll
            for (int h = 0; h < 2; h++) {
                float v = rs[mi][h];
                v += __shfl_xor_sync(0xffffffffu, v, 1);
                v += __shfl_xor_sync(0xffffffffu, v, 2);
                rs[mi][h] = v;
            }
        if (q == 0) {
#pragma unroll
            for (int mi = 0; mi < 2; mi++)
#pragma unroll
                for (int h = 0; h < 2; h++)
                    rp_s[wn * 128 + wm * 32 + mi * 16 + h * 8 + g] = rs[mi][h];
        }
        __syncthreads();
        if (t < 128)
            g_rpart[blockIdx.x][m0 + t] = rp_s[t] + rp_s[128 + t];
    } else {
        __half* pv = g_pv[blockIdx.z];
#pragma unroll
        for (int mi = 0; mi < 2; mi++) {
            int r0 = rbase + mi * 16 + g;
            __half2* d0 = (__half2*)(pv + (size_t)r0 * DIM);
            __half2* d1 = (__half2*)(pv + (size_t)(r0 + 8) * DIM);
#pragma unroll
            for (int nj = 0; nj < 8; nj++) {
                int c = cbase + nj * 8 + q * 2;
                d0[c >> 1] = __floats2half2_rn(acc[mi][nj][0], acc[mi][nj][1]);
                d1[c >> 1] = __floats2half2_rn(acc[mi][nj][2], acc[mi][nj][3]);
            }
        }
    }
}

// ---------------------------------------------------------------------------
// Launch
// ---------------------------------------------------------------------------
extern "C" void kernel_launch(void* const* d_in, const int* in_sizes, int n_in,
                              void* d_out, int out_size) {
    const float* Q = (const float*)d_in[0];   // [4096, 1024]
    const float* K = (const float*)d_in[1];   // [8192, 1024] (keys == values)
    float* out = (float*)d_out;               // [4096, 1024]
    (void)in_sizes; (void)n_in; (void)out_size;

    void *Qh, *Kh, *Vt, *R, *qn;
    cudaGetSymbolAddress(&Qh, g_Qh);
    cudaGetSymbolAddress(&Kh, g_Kh);
    cudaGetSymbolAddress(&Vt, g_Vt);
    cudaGetSymbolAddress(&R,  g_R);
    cudaGetSymbolAddress(&qn, g_qninv);

    cudaFuncSetAttribute(hgemm_kernel<0>, cudaFuncAttributeMaxDynamicSharedMemorySize, SMEM_BYTES);
    cudaFuncSetAttribute(hgemm_kernel<1>, cudaFuncAttributeMaxDynamicSharedMemorySize, SMEM_BYTES);

    convert_norm_kernel<<<NQ / 8, 256>>>(Q, (__half*)Qh, (float*)qn);
    fuse_k_kernel<<<dim3(DIM / 32, NK / 32), 256>>>(K);
    kfin_kernel<<<NK / 256, 256>>>();

    // GEMM1: R = exp(cos(Q,K)) - 1   [4096 x 8192] (+ fused row partials)
    hgemm_kernel<0><<<dim3(NK / BN, NQ / BM, 1), 256, SMEM_BYTES>>>(
        (const __half*)Qh, (const __half*)Kh, DIM, DIM, DIM, nullptr);

    // GEMM2 split-K: pv[z] = R[:, z*1024:(z+1)*1024] . Vt[:, same]  (fp16)
    hgemm_kernel<1><<<dim3(DIM / BN, NQ / BM, KSPLIT), 256, SMEM_BYTES>>>(
        (const __half*)R, (const __half*)Vt, NK, NK, NK / KSPLIT, nullptr);

    // out = (colsum + rowsum-from-rpart + sum pv) / rsum
    combine_kernel<<<NQ * DIM / 8 / 256, 256>>>(out);
}

// round 17
// speedup vs baseline: 1.0129x; 1.0129x over previous
#include <cuda_runtime.h>
#include <cuda_fp16.h>
#include <cstdint>

#define NQ 4096
#define NK 8192
#define DIM 1024
#define KSPLIT 8

// ---------------------------------------------------------------------------
// Scratch (device globals; no allocation in kernel_launch)
// ---------------------------------------------------------------------------
__device__ __half g_Qh[(size_t)NQ * DIM];     //  8 MB fp16 Q
__device__ __half g_Kh[(size_t)NK * DIM];     // 16 MB fp16 K (K-major)
__device__ __half g_Vt[(size_t)DIM * NK];     // 16 MB fp16 V^T [n][k]
__device__ __half g_R [(size_t)NQ * NK];      // 64 MB fp16 R = exp(cos)-1
__device__ __half g_pv[KSPLIT][(size_t)NQ * DIM];  // 64 MB fp16 PV partials
__device__ float  g_qninv[NQ];
__device__ float  g_kninv[NK];
__device__ float  g_rsum[NQ];
__device__ float  g_colsum[DIM];
__device__ float  g_knpart[32][NK];           // per-dim-strip |k|^2 partials
__device__ float  g_colpart[256][DIM];        // per-key-strip colsum partials
__device__ float  g_rpart[NK / 128][NQ];      // per-n-tile row partials (GEMM1)

// ---------------------------------------------------------------------------
// PTX helpers (plain sm_103-compatible: mma.sync / ldmatrix / cp.async)
// ---------------------------------------------------------------------------
__device__ __forceinline__ uint32_t smem_u32(const void* p) {
    uint32_t a;
    asm("{ .reg .u64 t; cvta.to.shared.u64 t, %1; cvt.u32.u64 %0, t; }"
        : "=r"(a) : "l"(p));
    return a;
}
__device__ __forceinline__ void cp16(uint32_t dst, const void* src) {
    asm volatile("cp.async.cg.shared.global [%0], [%1], 16;" :: "r"(dst), "l"(src));
}
#define CP_COMMIT() asm volatile("cp.async.commit_group;" ::: "memory")
#define CP_WAIT(N)  asm volatile("cp.async.wait_group %0;" :: "n"(N) : "memory")

__device__ __forceinline__ void ldsm_x4(uint32_t (&r)[4], uint32_t addr) {
    asm volatile("ldmatrix.sync.aligned.m8n8.x4.shared.b16 {%0,%1,%2,%3}, [%4];"
        : "=r"(r[0]), "=r"(r[1]), "=r"(r[2]), "=r"(r[3]) : "r"(addr));
}
__device__ __forceinline__ void mma16816(float (&d)[4], const uint32_t (&a)[4],
                                         uint32_t b0, uint32_t b1) {
    asm volatile("mma.sync.aligned.m16n8k16.row.col.f32.f16.f16.f32 "
        "{%0,%1,%2,%3}, {%4,%5,%6,%7}, {%8,%9}, {%0,%1,%2,%3};"
        : "+f"(d[0]), "+f"(d[1]), "+f"(d[2]), "+f"(d[3])
        : "r"(a[0]), "r"(a[1]), "r"(a[2]), "r"(a[3]), "r"(b0), "r"(b1));
}

// ---------------------------------------------------------------------------
// Aux kernels
// ---------------------------------------------------------------------------
__global__ void convert_norm_kernel(const float* __restrict__ X,
                                    __half* __restrict__ Xh,
                                    float* __restrict__ ninv) {
    int row  = blockIdx.x * 8 + (threadIdx.x >> 5);
    int lane = threadIdx.x & 31;
    const float4* xp = (const float4*)(X + (size_t)row * DIM);
    __half2* op = (__half2*)(Xh + (size_t)row * DIM);
    float s = 0.f;
#pragma unroll
    for (int i = 0; i < 8; i++) {
        float4 v = xp[lane + 32 * i];
        s += v.x * v.x + v.y * v.y + v.z * v.z + v.w * v.w;
        op[(lane + 32 * i) * 2]     = __floats2half2_rn(v.x, v.y);
        op[(lane + 32 * i) * 2 + 1] = __floats2half2_rn(v.z, v.w);
    }
#pragma unroll
    for (int o = 16; o > 0; o >>= 1) s += __shfl_xor_sync(0xffffffffu, s, o);
    if (lane == 0) ninv[row] = rsqrtf(s);
}

__global__ void fuse_k_kernel(const float* __restrict__ K) {
    __shared__ float tile[32][33];
    int n0 = blockIdx.x * 32, k0 = blockIdx.y * 32;
    int t = threadIdx.x;
    int krow = t >> 4;
    int c2   = t & 15;
#pragma unroll
    for (int p = 0; p < 2; p++) {
        int k = krow + 16 * p;
        float2 v = *(const float2*)(K + (size_t)(k0 + k) * DIM + n0 + 2 * c2);
        *(__half2*)(g_Kh + (size_t)(k0 + k) * DIM + n0 + 2 * c2) =
            __floats2half2_rn(v.x, v.y);
        tile[k][2 * c2]     = v.x;
        tile[k][2 * c2 + 1] = v.y;
    }
    __syncthreads();
    {
        int nrow = t >> 3;
        int kc   = t & 7;
#pragma unroll
        for (int p = 0; p < 2; p++) {
            int c = kc + 8 * p;
            __half2 h = __floats2half2_rn(tile[2 * c][nrow], tile[2 * c + 1][nrow]);
            *(__half2*)(g_Vt + (size_t)(n0 + nrow) * NK + k0 + 2 * c) = h;
        }
    }
    if (t < 32) {
        float s = 0.f;
#pragma unroll
        for (int j = 0; j < 32; j++) { float v = tile[t][j]; s += v * v; }
        g_knpart[blockIdx.x][k0 + t] = s;
    } else if (t < 64) {
        int c = t - 32;
        float s = 0.f;
#pragma unroll
        for (int j = 0; j < 32; j++) s += tile[j][c];
        g_colpart[blockIdx.y][n0 + c] = s;
    }
}

__global__ void kfin_kernel() {
    int gid = blockIdx.x * 256 + threadIdx.x;
    float s = 0.f;
#pragma unroll
    for (int j = 0; j < 32; j++) s += g_knpart[j][gid];
    g_kninv[gid] = rsqrtf(s);
    if (gid < DIM) {
        float c = 0.f;
        for (int j = 0; j < 256; j++) c += g_colpart[j][gid];
        g_colsum[gid] = c;
    }
}

__global__ void rowsum_fin_kernel() {
    int m = blockIdx.x * 256 + threadIdx.x;
    float s = (float)NK;
#pragma unroll
    for (int j = 0; j < NK / 128; j++) s += g_rpart[j][m];
    g_rsum[m] = s;
}

// out = (colsum + sum_s pv[s]) / rsum.  Each thread: one row-chunk of 8.
__global__ void combine_kernel(float* __restrict__ out) {
    int idx = blockIdx.x * 256 + threadIdx.x;       // over NQ*DIM/8
    int m  = idx / (DIM / 8);
    int c8 = (idx % (DIM / 8)) * 8;
    float ri = 1.0f / g_rsum[m];

    float s[8];
#pragma unroll
    for (int u = 0; u < 8; u++) s[u] = g_colsum[c8 + u];
#pragma unroll
    for (int sp = 0; sp < KSPLIT; sp++) {
        uint4 h4 = *(const uint4*)(g_pv[sp] + (size_t)m * DIM + c8);
        const __half2* h = (const __half2*)&h4;
#pragma unroll
        for (int u = 0; u < 4; u++) {
            float2 f = __half22float2(h[u]);
            s[2 * u] += f.x; s[2 * u + 1] += f.y;
        }
    }
    float4 o0 = make_float4(s[0] * ri, s[1] * ri, s[2] * ri, s[3] * ri);
    float4 o1 = make_float4(s[4] * ri, s[5] * ri, s[6] * ri, s[7] * ri);
    *(float4*)(out + (size_t)m * DIM + c8)     = o0;
    *(float4*)(out + (size_t)m * DIM + c8 + 4) = o1;
}

// ---------------------------------------------------------------------------
// HMMA fp16 GEMM: 128x128x64 tile, 256 threads, 3-stage cp.async, 2 CTA/SM.
// Warp grid 4(m) x 2(n); warp tile 32m x 64n (proven R10/R13 structure).
//   MODE 0: A=Qh[m][k], B=Kh[n][k], kdim=1024, grid z=1 (kstart folded to 0
//           at compile time); epi r=exp(acc*qninv*kninv)-1 -> g_R,
//           row partials -> g_rpart
//   MODE 1: A=R[m][k], B=Vt[n][k], kdim=1024 per split, grid z=KSPLIT;
//           epi: raw fp32 acc -> fp16 partial g_pv[z]
// ---------------------------------------------------------------------------
#define BM 128
#define BN 128
#define BK 64
#define STAGES 3
#define PITCHB 144                             // bytes per 64-half row
#define ST_A_BYTES (BM * PITCHB)               // 18432
#define ST_BYTES   (2 * ST_A_BYTES)            // 36864 (A + B)
#define SMEM_BYTES (STAGES * ST_BYTES + 1024)  // 111616 (stages + rp_s)

template <int MODE>
__global__ __launch_bounds__(256, 2) void hgemm_kernel(
    const __half* __restrict__ A, const __half* __restrict__ B,
    int lda, int ldb, int kdim, float* __restrict__ Cout) {
    extern __shared__ char smem[];
    const uint32_t sbase = smem_u32(smem);
    const int t = threadIdx.x;
    const int m0 = blockIdx.y * BM, n0 = blockIdx.x * BN;
    const int kstart = (MODE == 1) ? (int)blockIdx.z * kdim : 0;
    const int lane = t & 31, w = t >> 5;
    const int wm = w >> 1, wn = w & 1;          // 4 x 2 warp grid; tile 32m x 64n
    const int lrow = lane & 15, lcol = (lane >> 4) * 16;

    const int r_ld = t >> 3;
    const int c_ld = t & 7;
    const __half* aptr[4];
    const __half* bptr[4];
    uint32_t s_off[4];
#pragma unroll
    for (int j = 0; j < 4; j++) {
        int r = r_ld + 32 * j;
        aptr[j] = A + (size_t)(m0 + r) * lda + kstart + c_ld * 8;
        bptr[j] = B + (size_t)(n0 + r) * ldb + kstart + c_ld * 8;
        s_off[j] = r * PITCHB + c_ld * 16;
    }

    auto load_stage = [&](int ci, int st) {
        uint32_t sa = sbase + st * ST_BYTES;
        uint32_t sb = sa + ST_A_BYTES;
        int k0 = ci * BK;
#pragma unroll
        for (int j = 0; j < 4; j++) {
            cp16(sa + s_off[j], aptr[j] + k0);
            cp16(sb + s_off[j], bptr[j] + k0);
        }
    };

    float acc[2][8][4] = {};
    const int KT = kdim / BK;

    load_stage(0, 0); CP_COMMIT();
    load_stage(1, 1); CP_COMMIT();

    int st_cur = 0, st_nxt = 2;
    for (int i = 0; i < KT; i++) {
        CP_WAIT(1);
        __syncthreads();
        if (i + 2 < KT) { load_stage(i + 2, st_nxt); }
        CP_COMMIT();

        uint32_t sa = sbase + st_cur * ST_BYTES;
        uint32_t sb = sa + ST_A_BYTES;
        st_cur = (st_cur == STAGES - 1) ? 0 : st_cur + 1;
        st_nxt = (st_nxt == STAGES - 1) ? 0 : st_nxt + 1;

#pragma unroll
        for (int kk = 0; kk < 4; kk++) {
            uint32_t a[2][4], bf[4][4];
#pragma unroll
            for (int mi = 0; mi < 2; mi++) {
                int row = wm * 32 + mi * 16 + lrow;
                ldsm_x4(a[mi], sa + row * PITCHB + kk * 32 + lcol);
            }
#pragma unroll
            for (int ni = 0; ni < 4; ni++) {
                int row = wn * 64 + ni * 16 + lrow;
                ldsm_x4(bf[ni], sb + row * PITCHB + kk * 32 + lcol);
            }
#pragma unroll
            for (int mi = 0; mi < 2; mi++)
#pragma unroll
                for (int ni = 0; ni < 4; ni++) {
                    mma16816(acc[mi][2 * ni],     a[mi], bf[ni][0], bf[ni][2]);
                    mma16816(acc[mi][2 * ni + 1], a[mi], bf[ni][1], bf[ni][3]);
                }
        }
    }

    // ---- Epilogue ----
    const int g = lane >> 2, q = lane & 3;
    const int rbase = m0 + wm * 32;
    const int cbase = n0 + wn * 64;

    if (MODE == 0) {
        float* rp_s = (float*)(smem + STAGES * ST_BYTES);   // [2][128]
        float rs[2][2] = {};
        float kn[8][2];
#pragma unroll
        for (int nj = 0; nj < 8; nj++) {
            int c = cbase + nj * 8 + q * 2;
            kn[nj][0] = g_kninv[c]; kn[nj][1] = g_kninv[c + 1];
        }
#pragma unroll
        for (int mi = 0; mi < 2; mi++) {
            int r0 = rbase + mi * 16 + g;
            float qi0 = g_qninv[r0], qi1 = g_qninv[r0 + 8];
            __half2* d0 = (__half2*)(g_R + (size_t)r0 * NK);
            __half2* d1 = (__half2*)(g_R + (size_t)(r0 + 8) * NK);
#pragma unroll
            for (int nj = 0; nj < 8; nj++) {
                int c = cbase + nj * 8 + q * 2;
                float e00 = __expf(acc[mi][nj][0] * qi0 * kn[nj][0]) - 1.f;
                float e01 = __expf(acc[mi][nj][1] * qi0 * kn[nj][1]) - 1.f;
                float e10 = __expf(acc[mi][nj][2] * qi1 * kn[nj][0]) - 1.f;
                float e11 = __expf(acc[mi][nj][3] * qi1 * kn[nj][1]) - 1.f;
                rs[mi][0] += e00 + e01;
                rs[mi][1] += e10 + e11;
                d0[c >> 1] = __floats2half2_rn(e00, e01);
                d1[c >> 1] = __floats2half2_rn(e10, e11);
            }
        }
#pragma unroll
        for (int mi = 0; mi < 2; mi++)
#pragma unroll
            for (int h = 0; h < 2; h++) {
                float v = rs[mi][h];
                v += __shfl_xor_sync(0xffffffffu, v, 1);
                v += __shfl_xor_sync(0xffffffffu, v, 2);
                rs[mi][h] = v;
            }
        if (q == 0) {
#pragma unroll
            for (int mi = 0; mi < 2; mi++)
#pragma unroll
                for (int h = 0; h < 2; h++)
                    rp_s[wn * 128 + wm * 32 + mi * 16 + h * 8 + g] = rs[mi][h];
        }
        __syncthreads();
        if (t < 128)
            g_rpart[blockIdx.x][m0 + t] = rp_s[t] + rp_s[128 + t];
    } else {
        __half* pv = g_pv[blockIdx.z];
#pragma unroll
        for (int mi = 0; mi < 2; mi++) {
            int r0 = rbase + mi * 16 + g;
            __half2* d0 = (__half2*)(pv + (size_t)r0 * DIM);
            __half2* d1 = (__half2*)(pv + (size_t)(r0 + 8) * DIM);
#pragma unroll
            for (int nj = 0; nj < 8; nj++) {
                int c = cbase + nj * 8 + q * 2;
                d0[c >> 1] = __floats2half2_rn(acc[mi][nj][0], acc[mi][nj][1]);
                d1[c >> 1] = __floats2half2_rn(acc[mi][nj][2], acc[mi][nj][3]);
            }
        }
    }
}

// ---------------------------------------------------------------------------
// Launch
// ---------------------------------------------------------------------------
extern "C" void kernel_launch(void* const* d_in, const int* in_sizes, int n_in,
                              void* d_out, int out_size) {
    const float* Q = (const float*)d_in[0];   // [4096, 1024]
    const float* K = (const float*)d_in[1];   // [8192, 1024] (keys == values)
    float* out = (float*)d_out;               // [4096, 1024]
    (void)in_sizes; (void)n_in; (void)out_size;

    void *Qh, *Kh, *Vt, *R, *qn;
    cudaGetSymbolAddress(&Qh, g_Qh);
    cudaGetSymbolAddress(&Kh, g_Kh);
    cudaGetSymbolAddress(&Vt, g_Vt);
    cudaGetSymbolAddress(&R,  g_R);
    cudaGetSymbolAddress(&qn, g_qninv);

    cudaFuncSetAttribute(hgemm_kernel<0>, cudaFuncAttributeMaxDynamicSharedMemorySize, SMEM_BYTES);
    cudaFuncSetAttribute(hgemm_kernel<1>, cudaFuncAttributeMaxDynamicSharedMemorySize, SMEM_BYTES);

    convert_norm_kernel<<<NQ / 8, 256>>>(Q, (__half*)Qh, (float*)qn);
    fuse_k_kernel<<<dim3(DIM / 32, NK / 32), 256>>>(K);
    kfin_kernel<<<NK / 256, 256>>>();

    // GEMM1: R = exp(cos(Q,K)) - 1   [4096 x 8192] (+ fused row partials)
    hgemm_kernel<0><<<dim3(NK / BN, NQ / BM, 1), 256, SMEM_BYTES>>>(
        (const __half*)Qh, (const __half*)Kh, DIM, DIM, DIM, nullptr);

    rowsum_fin_kernel<<<NQ / 256, 256>>>();

    // GEMM2 split-K: pv[z] = R[:, z*1024:(z+1)*1024] . Vt[:, same]  (fp16)
    hgemm_kernel<1><<<dim3(DIM / BN, NQ / BM, KSPLIT), 256, SMEM_BYTES>>>(
        (const __half*)R, (const __half*)Vt, NK, NK, NK / KSPLIT, nullptr);

    // out = (colsum + sum pv) / rsum
    combine_kernel<<<NQ * DIM / 8 / 256, 256>>>(out);
}